// round 17
// baseline (speedup 1.0000x reference)
#include <cuda_runtime.h>
#include <cuda_bf16.h>
#include <cstdint>

#define BB     256
#define IN_F   1024
#define OUT_F  128
#define KD     16
#define NCOL   (OUT_F * KD)        // 2048
#define OUTW   (IN_F + OUT_F)      // 1152

#define SPLITS 4
#define KSPLIT (IN_F / SPLITS)     // 256
#define PSZ    (BB * NCOL)         // 524288 elems per split partial
#define BM     64
#define BN     64
#define BKK    32
#define NKT    (KSPLIT / BKK)      // 8
#define STAGES 3

#define A_STRIDE 80
#define B_STRIDE 144

#define QSPLIT 4                   // pair t-range slices

// exp(-s) == +0.0f exactly for s >= 105 (underflow cutoff ~104); partial L1
// sums are lower bounds, so screening is lossless.
#define THRESH 105.0f

__device__ __nv_bfloat16 d_pb[SPLITS * PSZ];     // bf16 partials [sp][o][b][k], 4 MB
__device__ __nv_bfloat16 d_tb[IN_F * NCOL];      // t in bf16, 4 MB
__device__ __nv_bfloat16 d_xb[BB * IN_F];        // x in bf16, 0.5 MB

__device__ __forceinline__ void cp16(uint32_t smem, const void* gmem) {
    asm volatile("cp.async.cg.shared.global [%0], [%1], 16;"
                 :: "r"(smem), "l"(gmem));
}

__device__ __forceinline__ uint32_t hadd2(uint32_t a, uint32_t b) {
    uint32_t r;
    asm("add.rn.bf16x2 %0, %1, %2;" : "=r"(r) : "r"(a), "r"(b));
    return r;
}

__device__ __forceinline__ void ldmat4(uint32_t& r0, uint32_t& r1,
                                       uint32_t& r2, uint32_t& r3,
                                       uint32_t addr) {
    asm volatile("ldmatrix.sync.aligned.m8n8.x4.shared.b16 {%0,%1,%2,%3}, [%4];"
                 : "=r"(r0), "=r"(r1), "=r"(r2), "=r"(r3) : "r"(addr));
}
__device__ __forceinline__ void ldmat4t(uint32_t& r0, uint32_t& r1,
                                        uint32_t& r2, uint32_t& r3,
                                        uint32_t addr) {
    asm volatile("ldmatrix.sync.aligned.m8n8.x4.trans.shared.b16 {%0,%1,%2,%3}, [%4];"
                 : "=r"(r0), "=r"(r1), "=r"(r2), "=r"(r3) : "r"(addr));
}

__device__ __forceinline__ uint32_t pack_bf16(float a, float b) {
    __nv_bfloat162 v = __floats2bfloat162_rn(a, b);
    return *(uint32_t*)&v;
}

// ---------------------------------------------------------------------------
// Convert t,x -> bf16 (64 B / thread, MLP=4) + x passthrough + o_b zero init.
// grid 704: [0,512) t-convert, [512,576) x-convert, [576,704) copy/init.
// ---------------------------------------------------------------------------
__global__ __launch_bounds__(256) void conv_kernel(
    const float* __restrict__ t, const float* __restrict__ x,
    __nv_bfloat16* __restrict__ tb, __nv_bfloat16* __restrict__ xb,
    float* __restrict__ out)
{
    const int tid = threadIdx.x;
    const int blk = blockIdx.x;

    if (blk < 576) {
        const float*   src = (blk < 512) ? t : x;
        __nv_bfloat16* dst = (blk < 512) ? tb : xb;
        const size_t gid = (size_t)(blk < 512 ? blk : blk - 512) * 256 + tid;
        const float4* s4 = (const float4*)src;
        // 4 independent 16B loads in flight before any use (MLP = 4)
        float4 v0 = s4[gid * 4 + 0];
        float4 v1 = s4[gid * 4 + 1];
        float4 v2 = s4[gid * 4 + 2];
        float4 v3 = s4[gid * 4 + 3];
        uint4 o0, o1;
        o0.x = pack_bf16(v0.x, v0.y); o0.y = pack_bf16(v0.z, v0.w);
        o0.z = pack_bf16(v1.x, v1.y); o0.w = pack_bf16(v1.z, v1.w);
        o1.x = pack_bf16(v2.x, v2.y); o1.y = pack_bf16(v2.z, v2.w);
        o1.z = pack_bf16(v3.x, v3.y); o1.w = pack_bf16(v3.z, v3.w);
        uint4* d4 = (uint4*)dst;
        d4[gid * 2 + 0] = o0;
        d4[gid * 2 + 1] = o1;
        return;
    }

    // copy/init: 128 blocks, 2 rows each
    const int id = blk - 576;
    const int r  = id * 2 + (tid >> 7);
    const int j  = tid & 127;
    const float4* src = (const float4*)(x + r * IN_F);
    float4*       dst = (float4*)(out + r * OUTW);
    dst[j]       = src[j];
    dst[j + 128] = src[j + 128];
    if (j < 32)   // diagonal never computed -> 0
        ((float4*)(out + r * OUTW + IN_F))[j] = make_float4(0.f, 0.f, 0.f, 0.f);
}

// ---------------------------------------------------------------------------
// GEMM via mma.sync m16n8k16 bf16: split-K x4, 64x64 tiles, 128 threads,
// ldmatrix, 3-stage cp.async ring. Epilogue writes bf16 partials [sp][o][b][k].
// ---------------------------------------------------------------------------
__global__ __launch_bounds__(128) void gemm_bf16_kernel(
    const __nv_bfloat16* __restrict__ A,
    const __nv_bfloat16* __restrict__ B,
    __nv_bfloat16* __restrict__ Cb)
{
    __shared__ char As[STAGES][BM * A_STRIDE];
    __shared__ char Bs[STAGES][BKK * B_STRIDE];

    const int tid  = threadIdx.x;
    const int lane = tid & 31;
    const int wid  = tid >> 5;
    const int g    = lane >> 2;
    const int t    = lane & 3;
    const int wm   = (wid >> 1) * 32;
    const int wn   = (wid & 1) * 32;
    const int bm0  = blockIdx.y * BM;
    const int bn0  = blockIdx.x * BN;
    const int koff = blockIdx.z * KSPLIT;

    const int lm = lane & 15;
    const int lh = (lane >> 4) & 1;

    const int arow = tid >> 2;
    const int ach  = tid & 3;
    const int brow = tid >> 3;
    const int bch  = tid & 7;

    uint32_t as_b[STAGES], bs_b[STAGES];
#pragma unroll
    for (int b = 0; b < STAGES; b++) {
        as_b[b] = (uint32_t)__cvta_generic_to_shared(&As[b][0]);
        bs_b[b] = (uint32_t)__cvta_generic_to_shared(&Bs[b][0]);
    }

    auto fetch = [&](int buf, int k0) {
#pragma unroll
        for (int i = 0; i < 2; i++) {
            const int r = arow + i * 32;
            cp16(as_b[buf] + r * A_STRIDE + ach * 16,
                 &A[(size_t)(bm0 + r) * IN_F + k0 + ach * 8]);
        }
#pragma unroll
        for (int i = 0; i < 2; i++) {
            const int r = brow + i * 16;
            cp16(bs_b[buf] + r * B_STRIDE + bch * 16,
                 &B[(size_t)(k0 + r) * NCOL + bn0 + bch * 8]);
        }
        asm volatile("cp.async.commit_group;");
    };

    float acc[2][4][4];
#pragma unroll
    for (int mf = 0; mf < 2; mf++)
#pragma unroll
        for (int nf = 0; nf < 4; nf++)
#pragma unroll
            for (int i = 0; i < 4; i++) acc[mf][nf][i] = 0.0f;

    fetch(0, koff);
    fetch(1, koff + BKK);

#pragma unroll 1
    for (int kt = 0; kt < NKT; kt++) {
        if (kt + 1 < NKT) asm volatile("cp.async.wait_group 1;");
        else              asm volatile("cp.async.wait_group 0;");
        __syncthreads();

        if (kt + 2 < NKT) fetch((kt + 2) % STAGES, koff + (kt + 2) * BKK);

        const int cur = kt % STAGES;
#pragma unroll
        for (int ks = 0; ks < 2; ks++) {
            uint32_t ua[2][4], ub[4][2];
#pragma unroll
            for (int mf = 0; mf < 2; mf++) {
                uint32_t addr = as_b[cur] + (wm + mf * 16 + lm) * A_STRIDE
                              + ks * 32 + lh * 16;
                ldmat4(ua[mf][0], ua[mf][1], ua[mf][2], ua[mf][3], addr);
            }
#pragma unroll
            for (int p = 0; p < 2; p++) {
                uint32_t addr = bs_b[cur] + (ks * 16 + lm) * B_STRIDE
                              + (wn + p * 16) * 2 + lh * 16;
                ldmat4t(ub[2 * p][0], ub[2 * p][1],
                        ub[2 * p + 1][0], ub[2 * p + 1][1], addr);
            }
#pragma unroll
            for (int mf = 0; mf < 2; mf++)
#pragma unroll
                for (int nf = 0; nf < 4; nf++) {
                    asm volatile(
                        "mma.sync.aligned.m16n8k16.row.col.f32.bf16.bf16.f32 "
                        "{%0,%1,%2,%3}, {%4,%5,%6,%7}, {%8,%9}, {%0,%1,%2,%3};\n"
                        : "+f"(acc[mf][nf][0]), "+f"(acc[mf][nf][1]),
                          "+f"(acc[mf][nf][2]), "+f"(acc[mf][nf][3])
                        : "r"(ua[mf][0]), "r"(ua[mf][1]),
                          "r"(ua[mf][2]), "r"(ua[mf][3]),
                          "r"(ub[nf][0]), "r"(ub[nf][1]));
                }
        }
    }

    __nv_bfloat16* Cz = Cb + blockIdx.z * PSZ;
#pragma unroll
    for (int mf = 0; mf < 2; mf++)
#pragma unroll
        for (int nf = 0; nf < 4; nf++) {
            const int r0 = bm0 + wm + mf * 16 + g;
            const int o  = ((bn0 + wn) >> 4) + (nf >> 1);
            const int k  = ((nf & 1) << 3) + t * 2;
            __nv_bfloat16* p = Cz + (size_t)o * (BB * KD) + k;
            *(uint32_t*)&p[(size_t)r0 * KD] =
                pack_bf16(acc[mf][nf][0], acc[mf][nf][1]);
            *(uint32_t*)&p[(size_t)(r0 + 8) * KD] =
                pack_bf16(acc[mf][nf][2], acc[mf][nf][3]);
        }
}

// ---------------------------------------------------------------------------
// Pairwise exp(-L1) in packed bf16x2 with fused split-K reduction preamble.
// Balanced cyclic triangle, 4 t-slices. grid (128 o, 4), 256 threads.
// ---------------------------------------------------------------------------
__global__ __launch_bounds__(256) void pair_kernel(
    const __nv_bfloat16* __restrict__ pb, float* __restrict__ out)
{
    __shared__ uint4 sm[2][BB];        // [chunk][b], negated bf16 rows, 8 KB

    const int o   = blockIdx.x;
    const int s   = blockIdx.y;
    const int b1  = threadIdx.x;
    const uint32_t SGN = 0x80008000u;
    const uint32_t MSK = 0x7FFF7FFFu;

    // o-slice = 512 uint4 chunks per split; sum 4 splits, negate, stage
    const uint4* po = (const uint4*)pb;   // PSZ/8 uint4 per split
    const int base = o * 512;
#pragma unroll
    for (int i = 0; i < 2; i++) {
        const int f = b1 + (i << 8);          // chunk index 0..511
        uint4 v = po[base + f];
#pragma unroll
        for (int sp = 1; sp < SPLITS; sp++) {
            uint4 w = po[sp * (PSZ / 8) + base + f];
            v.x = hadd2(v.x, w.x); v.y = hadd2(v.y, w.y);
            v.z = hadd2(v.z, w.z); v.w = hadd2(v.w, w.w);
        }
        v.x ^= SGN; v.y ^= SGN; v.z ^= SGN; v.w ^= SGN;
        sm[f & 1][f >> 1] = v;
    }
    __syncthreads();

    // own (positive) row
    uint32_t a[8];
    {
        uint4 v0 = sm[0][b1], v1 = sm[1][b1];
        a[0] = v0.x ^ SGN; a[1] = v0.y ^ SGN; a[2] = v0.z ^ SGN; a[3] = v0.w ^ SGN;
        a[4] = v1.x ^ SGN; a[5] = v1.y ^ SGN; a[6] = v1.z ^ SGN; a[7] = v1.w ^ SGN;
    }

    float* ob = out + IN_F + o;
    float tot = 0.0f;

    auto body = [&](int t) {
        const int b2 = (b1 + t) & 255;
        uint4 c = sm[0][b2];
        uint32_t d0 = hadd2(a[0], c.x) & MSK;
        uint32_t d1 = hadd2(a[1], c.y) & MSK;
        uint32_t d2 = hadd2(a[2], c.z) & MSK;
        uint32_t d3 = hadd2(a[3], c.w) & MSK;
        uint32_t f  = hadd2(hadd2(d0, d1), hadd2(d2, d3));
        float s8 = __uint_as_float(f << 16) + __uint_as_float(f & 0xFFFF0000u);

        if (s8 < THRESH) {               // else contribution is +0 exactly
            uint4 e = sm[1][b2];
            uint32_t d4 = hadd2(a[4], e.x) & MSK;
            uint32_t d5 = hadd2(a[5], e.y) & MSK;
            uint32_t d6 = hadd2(a[6], e.z) & MSK;
            uint32_t d7 = hadd2(a[7], e.w) & MSK;
            uint32_t g  = hadd2(hadd2(d4, d5), hadd2(d6, d7));
            float s16 = s8 + __uint_as_float(g << 16)
                           + __uint_as_float(g & 0xFFFF0000u);
            float ev = __expf(-s16);
            tot += ev;
            if (ev != 0.0f)              // credit the partner side
                atomicAdd(&ob[(size_t)b2 * OUTW], ev);
        }
    };

    // slices: t = 1+32s .. 32+32s  (s=3: ..127, then peel t=128 once)
    const int t0   = 1 + (s << 5);
    const int tend = (s == QSPLIT - 1) ? 128 : t0 + 32;
#pragma unroll 4
    for (int t = t0; t < tend; t++) body(t);
    if (s == QSPLIT - 1 && b1 < 128) body(128);

    if (tot != 0.0f)
        atomicAdd(&ob[(size_t)b1 * OUTW], tot);
}

extern "C" void kernel_launch(void* const* d_in, const int* in_sizes, int n_in,
                              void* d_out, int out_size)
{
    const float* x = (const float*)d_in[0];     // [256][1024]
    const float* t = (const float*)d_in[1];     // [1024][2048]
    float* out = (float*)d_out;                 // [256][1152]

    __nv_bfloat16* pb;    cudaGetSymbolAddress((void**)&pb, d_pb);
    __nv_bfloat16* tb;    cudaGetSymbolAddress((void**)&tb, d_tb);
    __nv_bfloat16* xb;    cudaGetSymbolAddress((void**)&xb, d_xb);

    conv_kernel<<<704, 256>>>(t, x, tb, xb, out);
    dim3 ggrid(NCOL / BN, BB / BM, SPLITS);      // (32, 4, 4)
    gemm_bf16_kernel<<<ggrid, 128>>>(xb, tb, pb);
    pair_kernel<<<dim3(OUT_F, QSPLIT), 256>>>(pb, out);
}